// round 16
// baseline (speedup 1.0000x reference)
#include <cuda_runtime.h>
#include <cuda_bf16.h>

// Patch2Im (col2im / fold): cooperative float4-staged gather.
// in : [256 (b*c), 7 (i), 7 (j), 85 (nh), 85 (nw)] f32
// out: [256, 253, 253] f32
//
// Block = output row h x 2 bc-planes. It consumes exactly 42 input rows
// (plane(2) x rowsel(3) x j(7)) of 85 contiguous floats each. Phase 1 stages
// them into smem with ALIGNED float4 LDGs. The 16B-align shift of a row is
// sh = (bcp*CPLANE + base_row) & 3 = (bc + 7ry + my + rx + 3c) & 3
// (CPLANE % 4 == PLANE % 4 == NHW % 4 == 1; 128*plane % 4 == 0; 20*rs % 4 == 0),
// so the shift is rowsel-independent and identical for both planes.
// Phase 2: residue-pure threads (rx = tid/96) sum <=9 slots x 2 planes from
// smem (pure-IADD indexing) and store directly (stride-3, as R13).
//
// Slots for output (h,w), y=h+3,x=w+3, ry=h%3, my=h/3+1, rx=w%3, m=w/3+1:
//   rowsel rs: i=ry+3rs, nh=my-rs; valid: rs0: my<=84, rs1: always,
//              rs2: ry==0 && my>=2
//   colsel c : j=rx+3c,  nw=m-c;   valid: c0: m<=84,  c1: always,
//              c2: rx==0 && m>=2

#define NHW 85
#define PLANE 7225
#define CPLANE (49 * PLANE)              // 354025 floats per (b,c) plane
#define WOUT 253
#define HOUT 253
#define SPATIAL (WOUT * HOUT)
#define NROWS 42                          // 2 planes * 3 rowsel * 7 j
#define ROWW 96                           // smem row width (floats)
#define NF4 (NROWS * 24)                  // 1008 float4 stage slots
#define TOTALF (256LL * CPLANE)           // total input floats

__global__ __launch_bounds__(288) void patch2im_kernel(
    const float* __restrict__ in, float* __restrict__ out)
{
    const int tid = threadIdx.x;
    const int h  = blockIdx.x;       // 0..252
    const int bc = blockIdx.y;       // planes bc, bc+128

    const int ry = h % 3;
    const int my = h / 3 + 1;        // 1..85
    const bool rvA = (my <= 84);
    const bool rvC = (ry == 0) && (my >= 2);

    __shared__ float sbuf[NROWS * ROWW];   // 16128 B

    // ---- Phase 1: stage 42 rows with aligned float4 loads ----
    for (int s = tid; s < NF4; s += 288) {
        const int r  = s / 24;
        const int c4 = s - r * 24;
        const int plane = r / 21;
        const int rr = r - plane * 21;
        const int rs = rr / 7;
        const int j  = rr - rs * 7;
        const bool valid = (rs == 1) | ((rs == 0) & rvA) | ((rs == 2) & rvC);
        if (valid) {
            const int i  = ry + 3 * rs;
            const int nh = my - rs;
            const int base_row = (i * 7 + j) * PLANE + nh * NHW;
            const int sh = (bc + base_row) & 3;   // bcp ≡ bc (mod 4)
            const long long g = (long long)(bc + plane * 128) * CPLANE
                              + (base_row - sh) + 4 * c4;
            float4 v = make_float4(0.f, 0.f, 0.f, 0.f);
            if (g + 4 <= TOTALF)
                v = __ldg((const float4*)(in + g));
            *(float4*)(sbuf + r * ROWW + 4 * c4) = v;
        }
    }
    __syncthreads();

    // ---- Phase 2: residue-pure gather from smem ----
    const int rx = tid / 96;         // 0,1,2 (warps residue-pure)
    const int t  = tid - rx * 96;    // 0..95
    const int m  = t + 1;
    const int mmax = (rx == 0) ? 85 : 84;
    if (m > mmax) return;

    const bool pcA = (m <= 84);
    const bool pcC = (rx == 0) && (m >= 2);

    // per-colsel smem column offsets: (rx+3c)*ROWW + sh_c + (m-c),
    // sh_c = (bc + 7ry + my + rx + 3c) & 3
    const int K7 = bc + 7 * ry + my;
    const int c0 = rx * ROWW       + ((K7 + rx)     & 3) + m;
    const int c1 = (rx + 3) * ROWW + ((K7 + rx + 3) & 3) + m - 1;
    const int c2 = (rx + 6) * ROWW + ((K7 + rx + 6) & 3) + m - 2;

    float acc0 = 0.f, acc1 = 0.f;    // plane0 / plane1
    #define P1OFF (21 * ROWW)

    {   // rowsel 0
        float a0=0.f,a1=0.f,a2=0.f,b0=0.f,b1=0.f,b2=0.f;
        if (rvA) {
            if (pcA) { a0 = sbuf[c0]; b0 = sbuf[P1OFF + c0]; }
                       a1 = sbuf[c1]; b1 = sbuf[P1OFF + c1];
            if (pcC) { a2 = sbuf[c2]; b2 = sbuf[P1OFF + c2]; }
        }
        acc0 += (a0 + a1) + a2;  acc1 += (b0 + b1) + b2;
    }
    {   // rowsel 1 (always valid)
        const int ro = 7 * ROWW;
        float a0=0.f,a1,a2=0.f,b0=0.f,b1,b2=0.f;
        if (pcA) { a0 = sbuf[ro + c0]; b0 = sbuf[P1OFF + ro + c0]; }
                   a1 = sbuf[ro + c1]; b1 = sbuf[P1OFF + ro + c1];
        if (pcC) { a2 = sbuf[ro + c2]; b2 = sbuf[P1OFF + ro + c2]; }
        acc0 += (a0 + a1) + a2;  acc1 += (b0 + b1) + b2;
    }
    {   // rowsel 2
        const int ro = 14 * ROWW;
        float a0=0.f,a1=0.f,a2=0.f,b0=0.f,b1=0.f,b2=0.f;
        if (rvC) {
            if (pcA) { a0 = sbuf[ro + c0]; b0 = sbuf[P1OFF + ro + c0]; }
                       a1 = sbuf[ro + c1]; b1 = sbuf[P1OFF + ro + c1];
            if (pcC) { a2 = sbuf[ro + c2]; b2 = sbuf[P1OFF + ro + c2]; }
        }
        acc0 += (a0 + a1) + a2;  acc1 += (b0 + b1) + b2;
    }

    const int cnt = (1 + (int)rvA + (int)rvC) * (1 + (int)pcA + (int)pcC);
    const float inv = 1.0f / (float)cnt;

    const int w = 3 * t + rx;        // output column (stride-3 within warp)
    const size_t obase = (size_t)bc * SPATIAL + (size_t)h * WOUT + w;
    out[obase] = acc0 * inv;
    out[obase + (size_t)128 * SPATIAL] = acc1 * inv;
}

extern "C" void kernel_launch(void* const* d_in, const int* in_sizes, int n_in,
                              void* d_out, int out_size)
{
    const float* in = (const float*)d_in[0];
    float* out = (float*)d_out;
    dim3 grid(HOUT, 128);   // (253 rows, 128 bc-pairs)
    patch2im_kernel<<<grid, 288>>>(in, out);
}

// round 17
// speedup vs baseline: 1.6583x; 1.6583x over previous
#include <cuda_runtime.h>
#include <cuda_bf16.h>

// Patch2Im (col2im / fold), residue-specialized gather, residue-pure warps,
// direct stride-3 stores. R13 structure + uniform-offset addressing:
// per-thread pointers qA/qB/qC (one IMAD.WIDE each), all 18 loads are
// q? + block-uniform offset (row0/1/2 and plane-1 displacement live in URs,
// so LDG uses the [R+UR] form with no per-load address build).
//
// in : [256 (b*c), 7 (i), 7 (j), 85 (nh), 85 (nw)] f32
// out: [256, 253, 253] f32
//
// Uncropped y = h + 3; contributing slots (i = y-3*nh):
//   A: i=ry,   nh=my    (valid iff my<=84)
//   B: i=ry+3, nh=my-1  (always)
//   C: i=ry+6, nh=my-2  (valid iff ry==0 && my>=2)
// ry=h%3, my=h/3+1; same structure in x with rx=w%3, m=w/3+1.
// Block: 288 threads, rx = tid/96 (warps residue-pure; every slot load is
// 32 consecutive floats). Output column w = 3*t + rx stored directly.

#define NHW 85
#define PLANE (NHW * NHW)        // 7225
#define CPLANE (49 * PLANE)      // floats per (b,c) plane
#define WOUT 253
#define HOUT 253
#define SPATIAL (WOUT * HOUT)

__global__ __launch_bounds__(288) void patch2im_kernel(
    const float* __restrict__ in, float* __restrict__ out)
{
    const int tid = threadIdx.x;
    const int h  = blockIdx.x;      // 0..252
    const int bc = blockIdx.y;      // 0..127 -> planes bc and bc+128

    // ---- row-uniform math (block-uniform -> uniform regs) ----
    const int ry = h % 3;
    const int my = h / 3 + 1;                  // 1..85
    const bool prA = (my <= 84);
    const bool prC = (ry == 0) && (my >= 2);
    const long long u0 = (ry * 7) * PLANE + my * NHW;          // row0
    const long long u1 = ((ry + 3) * 7) * PLANE + (my - 1) * NHW;
    const long long u2 = ((ry + 6) * 7) * PLANE + (my - 2) * NHW;
    const long long POFF = 128LL * CPLANE;     // plane-1 displacement
    const long long v0 = u0 + POFF, v1 = u1 + POFF, v2 = u2 + POFF;

    // ---- residue-pure per-thread mapping ----
    const int rx = tid / 96;        // 0,1,2  (96 = 3 full warps per residue)
    const int t  = tid - rx * 96;   // 0..95
    const int m  = t + 1;           // nw-index for slot A
    const int mmax = (rx == 0) ? 85 : 84;
    if (m > mmax) return;

    const bool pcA = (m <= 84);
    const bool pcC = (rx == 0) && (m >= 2);

    // per-thread base pointers (3 IMAD.WIDE total); all loads add uniform offs
    const float* __restrict__ p0 = in + (size_t)bc * CPLANE;
    const float* __restrict__ qA = p0 + (rx * PLANE + m);
    const float* __restrict__ qB = p0 + ((rx + 3) * PLANE + (m - 1));
    const float* __restrict__ qC = p0 + ((rx + 6) * PLANE + (m - 2));

    // ---- 9 predicated loads x 2 planes (independent -> MLP 18) ----
    float a0 = 0.f, a1 = 0.f, a2 = 0.f, a3 = 0.f, a4 = 0.f,
          a5 = 0.f, a6 = 0.f, a7 = 0.f, a8 = 0.f;
    float b0 = 0.f, b1 = 0.f, b2 = 0.f, b3 = 0.f, b4 = 0.f,
          b5 = 0.f, b6 = 0.f, b7 = 0.f, b8 = 0.f;

    if (prA && pcA) { a0 = __ldg(qA + u0); b0 = __ldg(qA + v0); }
    if (prA)        { a1 = __ldg(qB + u0); b1 = __ldg(qB + v0); }
    if (prA && pcC) { a2 = __ldg(qC + u0); b2 = __ldg(qC + v0); }
    if (pcA)        { a3 = __ldg(qA + u1); b3 = __ldg(qA + v1); }
    {               a4 = __ldg(qB + u1); b4 = __ldg(qB + v1); }
    if (pcC)        { a5 = __ldg(qC + u1); b5 = __ldg(qC + v1); }
    if (prC && pcA) { a6 = __ldg(qA + u2); b6 = __ldg(qA + v2); }
    if (prC)        { a7 = __ldg(qB + u2); b7 = __ldg(qB + v2); }
    if (prC && pcC) { a8 = __ldg(qC + u2); b8 = __ldg(qC + v2); }

    const int cnt = (1 + (int)prA + (int)prC) * (1 + (int)pcA + (int)pcC);
    const float inv = 1.0f / (float)cnt;

    const float s0 = ((a0 + a1) + (a2 + a3)) + ((a4 + a5) + (a6 + a7)) + a8;
    const float s1 = ((b0 + b1) + (b2 + b3)) + ((b4 + b5) + (b6 + b7)) + b8;

    const int w = 3 * t + rx;       // output column (stride-3 within warp)
    const size_t obase = (size_t)bc * SPATIAL + (size_t)h * WOUT + w;
    out[obase] = s0 * inv;
    out[obase + (size_t)128 * SPATIAL] = s1 * inv;
}

extern "C" void kernel_launch(void* const* d_in, const int* in_sizes, int n_in,
                              void* d_out, int out_size)
{
    const float* in = (const float*)d_in[0];
    float* out = (float*)d_out;
    dim3 grid(HOUT, 128);   // (253 rows, 128 bc-pairs)
    patch2im_kernel<<<grid, 288>>>(in, out);
}